// round 13
// baseline (speedup 1.0000x reference)
#include <cuda_runtime.h>
#include <cuda_bf16.h>

// LIF neuron forward over T=16 timesteps. FINAL KERNEL (session-converged).
// x: [B=16, C=64, T=16, H=64, W=64] fp32, decay: [1] fp32.
// out[b,c,t,h,w] = spike_t where:
//   mem_t = mem_{t-1} * sigmoid(decay) * (1 - spike_{t-1}) + x_t
//   spike_t = (mem_t > 0.5) ? 1 : 0
// (output clip is identity since spike in {0,1})
//
// Pure HBM-streaming kernel: 512 MB contractually irreducible traffic,
// zero reuse, saturating the B300's path-independent LTS/DRAM ceiling
// (~6.25 TB/s measured). Twelve-round converged configuration:
//   - 16-deep front-batched LDG.128.CS: .cs is load-bearing twice over —
//     it marks the stream evict-first in L2 AND prevents ptxas from
//     collapsing the batch back into an interleaved schedule (regs 80).
//   - sequential LIF recurrence on registers (compute pipes ~6% busy).
//   - 16-deep STG.128.CS write burst (.wt write-through and plain stores
//     both measured slower).
//   - 128-thread CTAs, 8192 blocks: granularity optimum (256 and 64
//     both measured slower at identical warps/SM); occupancy ~32% is
//     non-binding for this kernel at every tested level.
//   - flat grid (persistent grid-stride measured slower).
// Measured: 82.0 us harness (record), vs 84.0-86.8 for all alternatives.

#define T_STEPS 16
#define HW 4096                    // 64*64
#define BC 1024                    // 16*64
#define VEC4_PER_PLANE (HW / 4)    // 1024 float4 per (bc,t) plane
#define BLOCK 128

__global__ __launch_bounds__(BLOCK) void lif_kernel(
    const float* __restrict__ x,
    const float* __restrict__ decay,
    float* __restrict__ out)
{
    const float d  = decay[0];
    const float ds = 1.0f / (1.0f + __expf(-d));

    const unsigned g  = blockIdx.x * BLOCK + threadIdx.x;
    const unsigned bc = g >> 10;        // which (b,c) slab
    const unsigned s4 = g & 1023u;      // which float4 within the HW plane

    const size_t base = (size_t)bc * (T_STEPS * HW) + (size_t)s4 * 4;

    const float4* __restrict__ xin  = (const float4*)(x + base);
    float4* __restrict__ xout = (float4*)(out + base);

    // ---- phase 1: batch all 16 independent streaming loads (MLP=16) ----
    float4 xv[T_STEPS];
#pragma unroll
    for (int t = 0; t < T_STEPS; t++) {
        xv[t] = __ldcs(&xin[(size_t)t * VEC4_PER_PLANE]);
    }

    // ---- phase 2: sequential recurrence + streaming store burst ----
    float4 mem = make_float4(0.f, 0.f, 0.f, 0.f);
    float4 spk = make_float4(0.f, 0.f, 0.f, 0.f);

#pragma unroll
    for (int t = 0; t < T_STEPS; t++) {
        mem.x = mem.x * ds * (1.0f - spk.x) + xv[t].x;
        mem.y = mem.y * ds * (1.0f - spk.y) + xv[t].y;
        mem.z = mem.z * ds * (1.0f - spk.z) + xv[t].z;
        mem.w = mem.w * ds * (1.0f - spk.w) + xv[t].w;

        spk.x = (mem.x > 0.5f) ? 1.0f : 0.0f;
        spk.y = (mem.y > 0.5f) ? 1.0f : 0.0f;
        spk.z = (mem.z > 0.5f) ? 1.0f : 0.0f;
        spk.w = (mem.w > 0.5f) ? 1.0f : 0.0f;

        __stcs(&xout[(size_t)t * VEC4_PER_PLANE], spk);
    }
}

extern "C" void kernel_launch(void* const* d_in, const int* in_sizes, int n_in,
                              void* d_out, int out_size)
{
    const float* x     = (const float*)d_in[0];
    const float* decay = (const float*)d_in[1];
    float* out = (float*)d_out;

    const int blocks = (BC * VEC4_PER_PLANE) / BLOCK;  // 8192
    lif_kernel<<<blocks, BLOCK>>>(x, decay, out);
}

// round 14
// speedup vs baseline: 1.0039x; 1.0039x over previous
#include <cuda_runtime.h>
#include <cuda_bf16.h>

// LIF neuron forward over T=16 timesteps. FINAL KERNEL (session-converged,
// reproduced at 82.05/82.37 us; all alternatives 82.4-86.8 us).
// x: [B=16, C=64, T=16, H=64, W=64] fp32, decay: [1] fp32.
// out[b,c,t,h,w] = spike_t where:
//   mem_t = mem_{t-1} * sigmoid(decay) * (1 - spike_{t-1}) + x_t
//   spike_t = (mem_t > 0.5) ? 1 : 0
// (output clip is identity since spike in {0,1})
//
// Pure HBM-streaming kernel: 512 MB contractually irreducible traffic at
// ~6.25 TB/s, i.e. at the B300's path-independent LTS/DRAM ceiling.
// Thirteen-round converged configuration:
//   - 16-deep front-batched LDG.128.CS: .cs is load-bearing twice over —
//     it marks the stream evict-first in L2 AND prevents ptxas from
//     collapsing the batch back into an interleaved schedule (regs 80).
//   - sequential LIF recurrence on registers (compute pipes ~6% busy).
//   - 16-deep STG.128.CS write burst (.wt write-through and plain stores
//     both measured slower).
//   - 128-thread CTAs, 8192 blocks: granularity optimum (64 and 256
//     both measured slower at identical warps/SM); occupancy ~33% is
//     non-binding at every tested level (31-91%).
//   - flat grid (persistent grid-stride measured slower).

#define T_STEPS 16
#define HW 4096                    // 64*64
#define BC 1024                    // 16*64
#define VEC4_PER_PLANE (HW / 4)    // 1024 float4 per (bc,t) plane
#define BLOCK 128

__global__ __launch_bounds__(BLOCK) void lif_kernel(
    const float* __restrict__ x,
    const float* __restrict__ decay,
    float* __restrict__ out)
{
    const float d  = decay[0];
    const float ds = 1.0f / (1.0f + __expf(-d));

    const unsigned g  = blockIdx.x * BLOCK + threadIdx.x;
    const unsigned bc = g >> 10;        // which (b,c) slab
    const unsigned s4 = g & 1023u;      // which float4 within the HW plane

    const size_t base = (size_t)bc * (T_STEPS * HW) + (size_t)s4 * 4;

    const float4* __restrict__ xin  = (const float4*)(x + base);
    float4* __restrict__ xout = (float4*)(out + base);

    // ---- phase 1: batch all 16 independent streaming loads (MLP=16) ----
    float4 xv[T_STEPS];
#pragma unroll
    for (int t = 0; t < T_STEPS; t++) {
        xv[t] = __ldcs(&xin[(size_t)t * VEC4_PER_PLANE]);
    }

    // ---- phase 2: sequential recurrence + streaming store burst ----
    float4 mem = make_float4(0.f, 0.f, 0.f, 0.f);
    float4 spk = make_float4(0.f, 0.f, 0.f, 0.f);

#pragma unroll
    for (int t = 0; t < T_STEPS; t++) {
        mem.x = mem.x * ds * (1.0f - spk.x) + xv[t].x;
        mem.y = mem.y * ds * (1.0f - spk.y) + xv[t].y;
        mem.z = mem.z * ds * (1.0f - spk.z) + xv[t].z;
        mem.w = mem.w * ds * (1.0f - spk.w) + xv[t].w;

        spk.x = (mem.x > 0.5f) ? 1.0f : 0.0f;
        spk.y = (mem.y > 0.5f) ? 1.0f : 0.0f;
        spk.z = (mem.z > 0.5f) ? 1.0f : 0.0f;
        spk.w = (mem.w > 0.5f) ? 1.0f : 0.0f;

        __stcs(&xout[(size_t)t * VEC4_PER_PLANE], spk);
    }
}

extern "C" void kernel_launch(void* const* d_in, const int* in_sizes, int n_in,
                              void* d_out, int out_size)
{
    const float* x     = (const float*)d_in[0];
    const float* decay = (const float*)d_in[1];
    float* out = (float*)d_out;

    const int blocks = (BC * VEC4_PER_PLANE) / BLOCK;  // 8192
    lif_kernel<<<blocks, BLOCK>>>(x, decay, out);
}